// round 12
// baseline (speedup 1.0000x reference)
#include <cuda_runtime.h>
#include <cuda_bf16.h>
#include <cstdint>

// ---------------------------------------------------------------------------
// Problem constants (shapes are fixed by the dataset)
// ---------------------------------------------------------------------------
#define N_NODES   50000
#define N_EDGES   800000
#define DIM       128      // IN_DIM == OUT_DIM == 128
#define NUM_HEADS 8
#define HEAD_DIM  16

// ---------------------------------------------------------------------------
// Scratch (device globals; no allocation allowed in kernel_launch)
// ---------------------------------------------------------------------------
__device__ float g_Q[(size_t)N_NODES * DIM];
__device__ float g_K[(size_t)N_NODES * DIM];
__device__ float g_V[(size_t)N_NODES * DIM];
__device__ float g_Z[(size_t)N_NODES * NUM_HEADS];

// ---------------------------------------------------------------------------
// Shared GEMM mainloop: acc[8][8] += A_tile @ W_tile over K=128.
// 128x128 tile, BK=16, 256 threads, 8x8 microtile, double-buffered smem.
// Thread (tx,ty): rows ty*8..+7, cols tx*8..+7.  tid = ty*16 + tx.
// ---------------------------------------------------------------------------
#define BM 128
#define BN 128
#define BK 16
#define TM 8
#define TN 8
#define NKITER (DIM / BK)   // 8

__device__ __forceinline__
void gemm128_mainloop(const float* __restrict__ A, const float* __restrict__ W,
                      int M, int block_row, float acc[TM][TN])
{
    __shared__ float As[2][BK][BM + 1];   // [buf][k][m], +1 pad
    __shared__ float Bs[2][BK][BN];       // [buf][k][n]

    const int tid = threadIdx.x;               // 0..255

    // Per-thread load coordinates (fixed across iterations)
    const int ar0 = tid >> 2;                  // 0..63
    const int ar1 = ar0 + 64;                  // 64..127
    const int ac4 = (tid & 3) * 4;
    const int br0 = tid >> 5;                  // 0..7
    const int br1 = br0 + 8;                   // 8..15
    const int bc4 = (tid & 31) * 4;            // 0..124

#pragma unroll
    for (int i = 0; i < TM; i++)
#pragma unroll
        for (int j = 0; j < TN; j++) acc[i][j] = 0.f;

    const int gr0 = block_row + ar0;
    const int gr1 = block_row + ar1;
    const int tx = tid & 15;
    const int ty = tid >> 4;

    // ---- prologue: load tile 0 into buffer 0 ----
    {
        float4 a0 = make_float4(0.f, 0.f, 0.f, 0.f);
        float4 a1 = make_float4(0.f, 0.f, 0.f, 0.f);
        if (gr0 < M) a0 = *reinterpret_cast<const float4*>(A + (size_t)gr0 * DIM + ac4);
        if (gr1 < M) a1 = *reinterpret_cast<const float4*>(A + (size_t)gr1 * DIM + ac4);
        float4 b0 = *reinterpret_cast<const float4*>(W + (size_t)br0 * DIM + bc4);
        float4 b1 = *reinterpret_cast<const float4*>(W + (size_t)br1 * DIM + bc4);

        As[0][ac4 + 0][ar0] = a0.x; As[0][ac4 + 1][ar0] = a0.y;
        As[0][ac4 + 2][ar0] = a0.z; As[0][ac4 + 3][ar0] = a0.w;
        As[0][ac4 + 0][ar1] = a1.x; As[0][ac4 + 1][ar1] = a1.y;
        As[0][ac4 + 2][ar1] = a1.z; As[0][ac4 + 3][ar1] = a1.w;
        *reinterpret_cast<float4*>(&Bs[0][br0][bc4]) = b0;
        *reinterpret_cast<float4*>(&Bs[0][br1][bc4]) = b1;
    }
    __syncthreads();

#pragma unroll
    for (int t = 0; t < NKITER; t++) {
        const int cur = t & 1;
        const int nxt = cur ^ 1;

        // ---- prefetch tile t+1 into registers ----
        float4 pa0, pa1, pb0, pb1;
        if (t < NKITER - 1) {
            const int k0 = (t + 1) * BK;
            pa0 = make_float4(0.f, 0.f, 0.f, 0.f);
            pa1 = make_float4(0.f, 0.f, 0.f, 0.f);
            if (gr0 < M) pa0 = *reinterpret_cast<const float4*>(A + (size_t)gr0 * DIM + k0 + ac4);
            if (gr1 < M) pa1 = *reinterpret_cast<const float4*>(A + (size_t)gr1 * DIM + k0 + ac4);
            pb0 = *reinterpret_cast<const float4*>(W + (size_t)(k0 + br0) * DIM + bc4);
            pb1 = *reinterpret_cast<const float4*>(W + (size_t)(k0 + br1) * DIM + bc4);
        }

        // ---- compute on current buffer ----
#pragma unroll
        for (int k = 0; k < BK; k++) {
            float ra[TM], rb[TN];
#pragma unroll
            for (int i = 0; i < TM; i++) ra[i] = As[cur][k][ty * TM + i];
#pragma unroll
            for (int j = 0; j < TN; j++) rb[j] = Bs[cur][k][tx * TN + j];
#pragma unroll
            for (int i = 0; i < TM; i++)
#pragma unroll
                for (int j = 0; j < TN; j++)
                    acc[i][j] += ra[i] * rb[j];
        }

        // ---- store prefetched tile into other buffer, single barrier ----
        if (t < NKITER - 1) {
            As[nxt][ac4 + 0][ar0] = pa0.x; As[nxt][ac4 + 1][ar0] = pa0.y;
            As[nxt][ac4 + 2][ar0] = pa0.z; As[nxt][ac4 + 3][ar0] = pa0.w;
            As[nxt][ac4 + 0][ar1] = pa1.x; As[nxt][ac4 + 1][ar1] = pa1.y;
            As[nxt][ac4 + 2][ar1] = pa1.z; As[nxt][ac4 + 3][ar1] = pa1.w;
            *reinterpret_cast<float4*>(&Bs[nxt][br0][bc4]) = pb0;
            *reinterpret_cast<float4*>(&Bs[nxt][br1][bc4]) = pb1;
            __syncthreads();
        }
    }
}

// ---------------------------------------------------------------------------
// Fused QKV projection kernel (writes g_Q / g_K / g_V via grid.y)
// ---------------------------------------------------------------------------
__global__ __launch_bounds__(256)
void gemm_qkv(const float* __restrict__ x,
              const float* __restrict__ Wq, const float* __restrict__ bq,
              const float* __restrict__ Wk, const float* __restrict__ bk,
              const float* __restrict__ Wv, const float* __restrict__ bv,
              int M)
{
    const float* W; const float* b; float* C;
    if (blockIdx.y == 0)      { W = Wq; b = bq; C = g_Q; }
    else if (blockIdx.y == 1) { W = Wk; b = bk; C = g_K; }
    else                      { W = Wv; b = bv; C = g_V; }

    float acc[TM][TN];
    const int block_row = blockIdx.x * BM;
    gemm128_mainloop(x, W, M, block_row, acc);

    const int tid = threadIdx.x;
    const int tx = tid & 15;
    const int ty = tid >> 4;
#pragma unroll
    for (int i = 0; i < TM; i++) {
        int gr = block_row + ty * TM + i;
        if (gr < M) {
#pragma unroll
            for (int j = 0; j < TN; j += 4) {
                int col = tx * TN + j;
                float4 o;
                o.x = acc[i][j + 0] + __ldg(b + col + 0);
                o.y = acc[i][j + 1] + __ldg(b + col + 1);
                o.z = acc[i][j + 2] + __ldg(b + col + 2);
                o.w = acc[i][j + 3] + __ldg(b + col + 3);
                *reinterpret_cast<float4*>(C + (size_t)gr * DIM + col) = o;
            }
        }
    }
}

// ---------------------------------------------------------------------------
// FUSED edge kernel: E-projection GEMM + attention score + V-scatter.
// Never materializes E. In the epilogue, thread (tx,ty) holds E values for
// edges (block_row + ty*8 + i), cols tx*8..tx*8+7. A head h = tx>>1 spans the
// tx-pair {2h, 2h+1}; those two threads are lanes l and l^1 of the same warp
// (lane = (ty&1)*16 + tx), so shfl_xor(p,1) completes the 16-dim head dot.
// The e >= nE guard is uniform across the pair (same edge row), so the shfl
// is always executed by both partners. Scatter via red.global.add.v4.f32.
// ---------------------------------------------------------------------------
__global__ __launch_bounds__(256)
void gemm_edge_fused(const float* __restrict__ edge_attr,
                     const float* __restrict__ We,
                     const float* __restrict__ be,
                     const int*   __restrict__ ei,
                     float* __restrict__ out, int nE)
{
    float acc[TM][TN];
    const int block_row = blockIdx.x * BM;
    gemm128_mainloop(edge_attr, We, nE, block_row, acc);

    const int tid = threadIdx.x;
    const int tx = tid & 15;
    const int ty = tid >> 4;
    const int c0 = tx * TN;            // my 8 columns: c0..c0+7
    const int head = tx >> 1;          // head owning my columns

    // bias for my 8 columns (same for all rows)
    float bcol[TN];
#pragma unroll
    for (int j = 0; j < TN; j++) bcol[j] = __ldg(be + c0 + j);

#pragma unroll
    for (int i = 0; i < TM; i++) {
        const int e = block_row + ty * TM + i;
        if (e >= nE) continue;
        const int src = __ldg(ei + e);
        const int dst = __ldg(ei + nE + e);

        // gather K[src], Q[dst] for my 8 columns (two float4 each)
        const float4 k0 = *reinterpret_cast<const float4*>(g_K + (size_t)src * DIM + c0);
        const float4 k1 = *reinterpret_cast<const float4*>(g_K + (size_t)src * DIM + c0 + 4);
        const float4 q0 = *reinterpret_cast<const float4*>(g_Q + (size_t)dst * DIM + c0);
        const float4 q1 = *reinterpret_cast<const float4*>(g_Q + (size_t)dst * DIM + c0 + 4);

        // partial dot over my 8 cols: E * K * Q   (E = acc + bias)
        float p = (acc[i][0] + bcol[0]) * (k0.x * q0.x)
                + (acc[i][1] + bcol[1]) * (k0.y * q0.y)
                + (acc[i][2] + bcol[2]) * (k0.z * q0.z)
                + (acc[i][3] + bcol[3]) * (k0.w * q0.w)
                + (acc[i][4] + bcol[4]) * (k1.x * q1.x)
                + (acc[i][5] + bcol[5]) * (k1.y * q1.y)
                + (acc[i][6] + bcol[6]) * (k1.z * q1.z)
                + (acc[i][7] + bcol[7]) * (k1.w * q1.w);

        // complete the 16-dim head sum with the tx-pair partner
        p += __shfl_xor_sync(0xffffffffu, p, 1);

        // score = exp(clip(sum / sqrt(16), -5, 5))
        const float s = __expf(fminf(fmaxf(p * 0.25f, -5.f), 5.f));

        // message: V[src, my cols] * s, scattered to out[dst, my cols]
        const float4 v0 = *reinterpret_cast<const float4*>(g_V + (size_t)src * DIM + c0);
        const float4 v1 = *reinterpret_cast<const float4*>(g_V + (size_t)src * DIM + c0 + 4);

        float* addr0 = out + (size_t)dst * DIM + c0;
        asm volatile("red.global.add.v4.f32 [%0], {%1, %2, %3, %4};"
                     :: "l"(addr0), "f"(v0.x * s), "f"(v0.y * s), "f"(v0.z * s), "f"(v0.w * s)
                     : "memory");
        asm volatile("red.global.add.v4.f32 [%0], {%1, %2, %3, %4};"
                     :: "l"(addr0 + 4), "f"(v1.x * s), "f"(v1.y * s), "f"(v1.z * s), "f"(v1.w * s)
                     : "memory");

        // denominator: one lane of the tx-pair contributes s per head
        if ((tx & 1) == 0)
            atomicAdd(&g_Z[(size_t)dst * NUM_HEADS + head], s);
    }
}

// ---------------------------------------------------------------------------
// Zero the accumulators (d_out used as wV accumulator, g_Z for denominators)
// ---------------------------------------------------------------------------
__global__ void zero_kernel(float* __restrict__ out)
{
    size_t i = (size_t)blockIdx.x * blockDim.x + threadIdx.x;
    if (i < (size_t)N_NODES * DIM) out[i] = 0.f;
    if (i < (size_t)N_NODES * NUM_HEADS) g_Z[i] = 0.f;
}

// ---------------------------------------------------------------------------
// Normalize: out[n, :] /= (Z[n, head] + 1e-6)
// ---------------------------------------------------------------------------
__global__ void norm_kernel(float* __restrict__ out)
{
    int i = blockIdx.x * blockDim.x + threadIdx.x;       // float4 index
    const int total = N_NODES * (DIM / 4);               // 50000 * 32
    if (i >= total) return;
    int n = i >> 5;            // node
    int q = i & 31;            // float4-within-row; head = q >> 2
    float z = g_Z[(size_t)n * NUM_HEADS + (q >> 2)];
    float invz = 1.f / (z + 1e-6f);
    float4* p = reinterpret_cast<float4*>(out) + i;
    float4 v = *p;
    v.x *= invz; v.y *= invz; v.z *= invz; v.w *= invz;
    *p = v;
}

// ---------------------------------------------------------------------------
// kernel_launch
// Inputs (metadata order):
//  0: x          [N, 128] f32
//  1: edge_attr  [E, 128] f32
//  2: edge_index [2, E]   i32
//  3: Wq [128,128]  4: bq [128]
//  5: Wk [128,128]  6: bk [128]
//  7: We [128,128]  8: be [128]
//  9: Wv [128,128] 10: bv [128]
// Output: [N, 128] f32
// ---------------------------------------------------------------------------
extern "C" void kernel_launch(void* const* d_in, const int* in_sizes, int n_in,
                              void* d_out, int out_size)
{
    const float* x         = (const float*)d_in[0];
    const float* edge_attr = (const float*)d_in[1];
    const int*   edge_idx  = (const int*)  d_in[2];
    const float* Wq = (const float*)d_in[3];
    const float* bq = (const float*)d_in[4];
    const float* Wk = (const float*)d_in[5];
    const float* bk = (const float*)d_in[6];
    const float* We = (const float*)d_in[7];
    const float* be = (const float*)d_in[8];
    const float* Wv = (const float*)d_in[9];
    const float* bv = (const float*)d_in[10];
    float* out = (float*)d_out;

    const int nNodes = in_sizes[0] / DIM;     // 50000
    const int nE     = in_sizes[1] / DIM;     // 800000

    // zero accumulators (covers both out and g_Z since N*8 < N*128)
    {
        size_t total = (size_t)nNodes * DIM;
        int threads = 256;
        int blocks = (int)((total + threads - 1) / threads);
        zero_kernel<<<blocks, threads>>>(out);
    }

    // node projections Q, K, V (fused into one launch; grid.y = which proj)
    {
        dim3 grid((nNodes + BM - 1) / BM, 3);
        gemm_qkv<<<grid, 256>>>(x, Wq, bq, Wk, bk, Wv, bv, nNodes);
    }

    // fused: E projection + attention score + scatter (E never materialized)
    {
        int blocks = (nE + BM - 1) / BM;      // 6250
        gemm_edge_fused<<<blocks, 256>>>(edge_attr, We, be, edge_idx, out, nE);
    }

    // normalize
    {
        int total = nNodes * (DIM / 4);
        int threads = 256;
        int blocks = (total + threads - 1) / threads;
        norm_kernel<<<blocks, threads>>>(out);
    }
}

// round 17
// speedup vs baseline: 1.2622x; 1.2622x over previous
#include <cuda_runtime.h>
#include <cuda_bf16.h>
#include <cstdint>

// ---------------------------------------------------------------------------
// Problem constants
// ---------------------------------------------------------------------------
#define N_NODES   50000
#define N_EDGES   800000
#define DIM       128
#define NUM_HEADS 8
#define HEAD_DIM  16

// ---------------------------------------------------------------------------
// Scratch (device globals)
// ---------------------------------------------------------------------------
__device__ float g_Q[(size_t)N_NODES * DIM];
__device__ float g_K[(size_t)N_NODES * DIM];
__device__ float g_V[(size_t)N_NODES * DIM];
__device__ float g_E[(size_t)N_EDGES * DIM];
__device__ float g_Z[(size_t)N_NODES * NUM_HEADS];

// ---------------------------------------------------------------------------
// Scalar fp32 GEMM (QKV only: 3 x [50000,128]@[128,128], ~75us measured)
// ---------------------------------------------------------------------------
#define BM 128
#define BK 16
#define TM 8
#define TN 8
#define NKITER (DIM / BK)

__device__ __forceinline__
void gemm128_mainloop(const float* __restrict__ A, const float* __restrict__ W,
                      int M, int block_row, float acc[TM][TN])
{
    __shared__ float As[2][BK][BM + 1];
    __shared__ float Bs[2][BK][BM];

    const int tid = threadIdx.x;
    const int ar0 = tid >> 2;
    const int ar1 = ar0 + 64;
    const int ac4 = (tid & 3) * 4;
    const int br0 = tid >> 5;
    const int br1 = br0 + 8;
    const int bc4 = (tid & 31) * 4;

#pragma unroll
    for (int i = 0; i < TM; i++)
#pragma unroll
        for (int j = 0; j < TN; j++) acc[i][j] = 0.f;

    const int gr0 = block_row + ar0;
    const int gr1 = block_row + ar1;
    const int tx = tid & 15;
    const int ty = tid >> 4;

    {
        float4 a0 = make_float4(0.f, 0.f, 0.f, 0.f);
        float4 a1 = make_float4(0.f, 0.f, 0.f, 0.f);
        if (gr0 < M) a0 = *reinterpret_cast<const float4*>(A + (size_t)gr0 * DIM + ac4);
        if (gr1 < M) a1 = *reinterpret_cast<const float4*>(A + (size_t)gr1 * DIM + ac4);
        float4 b0 = *reinterpret_cast<const float4*>(W + (size_t)br0 * DIM + bc4);
        float4 b1 = *reinterpret_cast<const float4*>(W + (size_t)br1 * DIM + bc4);

        As[0][ac4 + 0][ar0] = a0.x; As[0][ac4 + 1][ar0] = a0.y;
        As[0][ac4 + 2][ar0] = a0.z; As[0][ac4 + 3][ar0] = a0.w;
        As[0][ac4 + 0][ar1] = a1.x; As[0][ac4 + 1][ar1] = a1.y;
        As[0][ac4 + 2][ar1] = a1.z; As[0][ac4 + 3][ar1] = a1.w;
        *reinterpret_cast<float4*>(&Bs[0][br0][bc4]) = b0;
        *reinterpret_cast<float4*>(&Bs[0][br1][bc4]) = b1;
    }
    __syncthreads();

#pragma unroll
    for (int t = 0; t < NKITER; t++) {
        const int cur = t & 1;
        const int nxt = cur ^ 1;

        float4 pa0, pa1, pb0, pb1;
        if (t < NKITER - 1) {
            const int k0 = (t + 1) * BK;
            pa0 = make_float4(0.f, 0.f, 0.f, 0.f);
            pa1 = make_float4(0.f, 0.f, 0.f, 0.f);
            if (gr0 < M) pa0 = *reinterpret_cast<const float4*>(A + (size_t)gr0 * DIM + k0 + ac4);
            if (gr1 < M) pa1 = *reinterpret_cast<const float4*>(A + (size_t)gr1 * DIM + k0 + ac4);
            pb0 = *reinterpret_cast<const float4*>(W + (size_t)(k0 + br0) * DIM + bc4);
            pb1 = *reinterpret_cast<const float4*>(W + (size_t)(k0 + br1) * DIM + bc4);
        }

#pragma unroll
        for (int k = 0; k < BK; k++) {
            float ra[TM], rb[TN];
#pragma unroll
            for (int i = 0; i < TM; i++) ra[i] = As[cur][k][ty * TM + i];
#pragma unroll
            for (int j = 0; j < TN; j++) rb[j] = Bs[cur][k][tx * TN + j];
#pragma unroll
            for (int i = 0; i < TM; i++)
#pragma unroll
                for (int j = 0; j < TN; j++)
                    acc[i][j] += ra[i] * rb[j];
        }

        if (t < NKITER - 1) {
            As[nxt][ac4 + 0][ar0] = pa0.x; As[nxt][ac4 + 1][ar0] = pa0.y;
            As[nxt][ac4 + 2][ar0] = pa0.z; As[nxt][ac4 + 3][ar0] = pa0.w;
            As[nxt][ac4 + 0][ar1] = pa1.x; As[nxt][ac4 + 1][ar1] = pa1.y;
            As[nxt][ac4 + 2][ar1] = pa1.z; As[nxt][ac4 + 3][ar1] = pa1.w;
            *reinterpret_cast<float4*>(&Bs[nxt][br0][bc4]) = pb0;
            *reinterpret_cast<float4*>(&Bs[nxt][br1][bc4]) = pb1;
            __syncthreads();
        }
    }
}

__global__ __launch_bounds__(256)
void gemm_qkv(const float* __restrict__ x,
              const float* __restrict__ Wq, const float* __restrict__ bq,
              const float* __restrict__ Wk, const float* __restrict__ bk,
              const float* __restrict__ Wv, const float* __restrict__ bv,
              int M)
{
    const float* W; const float* b; float* C;
    if (blockIdx.y == 0)      { W = Wq; b = bq; C = g_Q; }
    else if (blockIdx.y == 1) { W = Wk; b = bk; C = g_K; }
    else                      { W = Wv; b = bv; C = g_V; }

    float acc[TM][TN];
    const int block_row = blockIdx.x * BM;
    gemm128_mainloop(x, W, M, block_row, acc);

    const int tid = threadIdx.x;
    const int tx = tid & 15;
    const int ty = tid >> 4;
#pragma unroll
    for (int i = 0; i < TM; i++) {
        int gr = block_row + ty * TM + i;
        if (gr < M) {
#pragma unroll
            for (int j = 0; j < TN; j += 4) {
                int col = tx * TN + j;
                float4 o;
                o.x = acc[i][j + 0] + __ldg(b + col + 0);
                o.y = acc[i][j + 1] + __ldg(b + col + 1);
                o.z = acc[i][j + 2] + __ldg(b + col + 2);
                o.w = acc[i][j + 3] + __ldg(b + col + 3);
                *reinterpret_cast<float4*>(C + (size_t)gr * DIM + col) = o;
            }
        }
    }
}

// ---------------------------------------------------------------------------
// TENSOR-CORE E projection via baseline mma.sync (sm_80+ ISA; no 'a' features).
// g_E = edge_attr @ We + be, bf16x3 (Ah*Wh + Ah*Wl + Al*Wh), fp32 acc.
// Tile 128x128 per CTA, 8 warps in 4(M) x 2(N); warp tile 32x64 =
// 2 x 8 m16n8k16 fragments. Fragments loaded by direct LDS per the PTX
// fragment layout (groupID = lane>>2, tg = lane&3):
//   A: a0 (row g,   k tg*2), a1 (row g+8, k tg*2), a2 (g, k+8), a3 (g+8, k+8)
//   B: b0 (k tg*2, n g), b1 (k tg*2+8, n g)   [B stored as Wt[n][k]]
//   C: c0,c1 (row g, col tg*2 +0/1), c2,c3 (row g+8)
// SMEM stride 136 halfs = 68 words = 4 mod 32 -> bank (4g+tg): conflict-free.
// ---------------------------------------------------------------------------
#define AS 136
#define SM_AH 0
#define SM_AL (128 * AS)
#define SM_WH (2 * 128 * AS)
#define SM_WL (3 * 128 * AS)
#define EMM_SMEM (4 * 128 * AS * 2)   // 139264 bytes

__device__ __forceinline__ void mma_bf16(float c[4], const uint32_t a[4],
                                         uint32_t b0, uint32_t b1)
{
    asm volatile(
        "mma.sync.aligned.m16n8k16.row.col.f32.bf16.bf16.f32 "
        "{%0,%1,%2,%3}, {%4,%5,%6,%7}, {%8,%9}, {%0,%1,%2,%3};"
        : "+f"(c[0]), "+f"(c[1]), "+f"(c[2]), "+f"(c[3])
        : "r"(a[0]), "r"(a[1]), "r"(a[2]), "r"(a[3]), "r"(b0), "r"(b1));
}

__global__ __launch_bounds__(256, 1)
void gemm_e_mma(const float* __restrict__ A, const float* __restrict__ W,
                const float* __restrict__ bias, int nE)
{
    extern __shared__ __nv_bfloat16 sm[];
    const int tid  = threadIdx.x;
    const int wid  = tid >> 5;
    const int lane = tid & 31;
    const int g    = lane >> 2;
    const int tg   = lane & 3;
    const int block_row = blockIdx.x * 128;

    // ---- stage A tile (hi/lo split), rows 0..127, cols 0..127 ----
    for (int idx = tid; idx < 8192; idx += 256) {
        const int row = idx >> 6;          // 0..127
        const int c2  = idx & 63;          // float2 index -> cols 2c2, 2c2+1
        const int gr  = block_row + row;
        float2 v = make_float2(0.f, 0.f);
        if (gr < nE) v = *reinterpret_cast<const float2*>(A + (size_t)gr * 128 + c2 * 2);
        __nv_bfloat16 hx = __float2bfloat16(v.x);
        __nv_bfloat16 hy = __float2bfloat16(v.y);
        __nv_bfloat16 lx = __float2bfloat16(v.x - __bfloat162float(hx));
        __nv_bfloat16 ly = __float2bfloat16(v.y - __bfloat162float(hy));
        __nv_bfloat162 h2; h2.x = hx; h2.y = hy;
        __nv_bfloat162 l2; l2.x = lx; l2.y = ly;
        const int off = row * AS + c2 * 2;
        *reinterpret_cast<__nv_bfloat162*>(&sm[SM_AH + off]) = h2;
        *reinterpret_cast<__nv_bfloat162*>(&sm[SM_AL + off]) = l2;
    }

    // ---- stage W transposed (hi/lo): Wt[n][k] = We[k][n] ----
    for (int idx = tid; idx < 16384; idx += 256) {
        const int k = idx >> 7;            // We row (coalesced read)
        const int n = idx & 127;
        float v = __ldg(W + (size_t)k * 128 + n);
        __nv_bfloat16 h = __float2bfloat16(v);
        __nv_bfloat16 l = __float2bfloat16(v - __bfloat162float(h));
        const int off = n * AS + k;
        sm[SM_WH + off] = h;
        sm[SM_WL + off] = l;
    }
    __syncthreads();

    // ---- mainloop ----
    const int warpM = wid & 3;             // 0..3
    const int warpN = wid >> 2;            // 0..1
    const int rowbase = warpM * 32;
    const int colbase = warpN * 64;

    float c[2][8][4];
#pragma unroll
    for (int mi = 0; mi < 2; mi++)
#pragma unroll
        for (int nj = 0; nj < 8; nj++)
#pragma unroll
            for (int q = 0; q < 4; q++) c[mi][nj][q] = 0.f;

    for (int ks = 0; ks < 8; ks++) {
        const int kbase = ks * 16 + tg * 2;

        uint32_t ah[2][4], al[2][4];
#pragma unroll
        for (int mi = 0; mi < 2; mi++) {
            const int r = rowbase + mi * 16 + g;
            ah[mi][0] = *reinterpret_cast<const uint32_t*>(&sm[SM_AH + r * AS + kbase]);
            ah[mi][1] = *reinterpret_cast<const uint32_t*>(&sm[SM_AH + (r + 8) * AS + kbase]);
            ah[mi][2] = *reinterpret_cast<const uint32_t*>(&sm[SM_AH + r * AS + kbase + 8]);
            ah[mi][3] = *reinterpret_cast<const uint32_t*>(&sm[SM_AH + (r + 8) * AS + kbase + 8]);
            al[mi][0] = *reinterpret_cast<const uint32_t*>(&sm[SM_AL + r * AS + kbase]);
            al[mi][1] = *reinterpret_cast<const uint32_t*>(&sm[SM_AL + (r + 8) * AS + kbase]);
            al[mi][2] = *reinterpret_cast<const uint32_t*>(&sm[SM_AL + r * AS + kbase + 8]);
            al[mi][3] = *reinterpret_cast<const uint32_t*>(&sm[SM_AL + (r + 8) * AS + kbase + 8]);
        }

#pragma unroll
        for (int nj = 0; nj < 8; nj++) {
            const int n = colbase + nj * 8 + g;
            const uint32_t bh0 = *reinterpret_cast<const uint32_t*>(&sm[SM_WH + n * AS + kbase]);
            const uint32_t bh1 = *reinterpret_cast<const uint32_t*>(&sm[SM_WH + n * AS + kbase + 8]);
            const uint32_t bl0 = *reinterpret_cast<const uint32_t*>(&sm[SM_WL + n * AS + kbase]);
            const uint32_t bl1 = *reinterpret_cast<const uint32_t*>(&sm[SM_WL + n * AS + kbase + 8]);
#pragma unroll
            for (int mi = 0; mi < 2; mi++) {
                mma_bf16(c[mi][nj], ah[mi], bh0, bh1);   // Ah * Wh
                mma_bf16(c[mi][nj], ah[mi], bl0, bl1);   // Ah * Wl
                mma_bf16(c[mi][nj], al[mi], bh0, bh1);   // Al * Wh
            }
        }
    }

    // ---- epilogue: bias + store fp32 E ----
#pragma unroll
    for (int mi = 0; mi < 2; mi++) {
#pragma unroll
        for (int nj = 0; nj < 8; nj++) {
            const int col = colbase + nj * 8 + tg * 2;
            const float bx = __ldg(bias + col);
            const float by = __ldg(bias + col + 1);
            const int r0 = block_row + rowbase + mi * 16 + g;
            if (r0 < nE) {
                float2 o; o.x = c[mi][nj][0] + bx; o.y = c[mi][nj][1] + by;
                *reinterpret_cast<float2*>(g_E + (size_t)r0 * 128 + col) = o;
            }
            const int r1 = r0 + 8;
            if (r1 < nE) {
                float2 o; o.x = c[mi][nj][2] + bx; o.y = c[mi][nj][3] + by;
                *reinterpret_cast<float2*>(g_E + (size_t)r1 * 128 + col) = o;
            }
        }
    }
}

// ---------------------------------------------------------------------------
// Edge attention (R4-measured: 228us, occ 60%): warp per edge, grid-stride.
// ---------------------------------------------------------------------------
__global__ __launch_bounds__(256)
void edge_kernel(const int* __restrict__ ei, float* __restrict__ out, int nE)
{
    const int lane   = threadIdx.x & 31;
    const int warpId = (int)((blockIdx.x * blockDim.x + threadIdx.x) >> 5);
    const int nWarps = (int)((gridDim.x * blockDim.x) >> 5);
    const int fo     = lane * 4;

    for (int e = warpId; e < nE; e += nWarps) {
        const int src = __ldg(ei + e);
        const int dst = __ldg(ei + nE + e);

        const float4 e4 = *reinterpret_cast<const float4*>(g_E + (size_t)e   * DIM + fo);
        const float4 k4 = *reinterpret_cast<const float4*>(g_K + (size_t)src * DIM + fo);
        const float4 q4 = *reinterpret_cast<const float4*>(g_Q + (size_t)dst * DIM + fo);

        float p = e4.x * (k4.x * q4.x)
                + e4.y * (k4.y * q4.y)
                + e4.z * (k4.z * q4.z)
                + e4.w * (k4.w * q4.w);
        p += __shfl_xor_sync(0xffffffffu, p, 1);
        p += __shfl_xor_sync(0xffffffffu, p, 2);

        const float s = __expf(fminf(fmaxf(p * 0.25f, -5.f), 5.f));

        const float4 v4 = *reinterpret_cast<const float4*>(g_V + (size_t)src * DIM + fo);
        float* addr = out + (size_t)dst * DIM + fo;
        asm volatile("red.global.add.v4.f32 [%0], {%1, %2, %3, %4};"
                     :: "l"(addr), "f"(v4.x * s), "f"(v4.y * s), "f"(v4.z * s), "f"(v4.w * s)
                     : "memory");

        if ((lane & 3) == 0)
            atomicAdd(&g_Z[(size_t)dst * NUM_HEADS + (lane >> 2)], s);
    }
}

// ---------------------------------------------------------------------------
__global__ void zero_kernel(float* __restrict__ out)
{
    size_t i = (size_t)blockIdx.x * blockDim.x + threadIdx.x;
    if (i < (size_t)N_NODES * DIM) out[i] = 0.f;
    if (i < (size_t)N_NODES * NUM_HEADS) g_Z[i] = 0.f;
}

__global__ void norm_kernel(float* __restrict__ out)
{
    int i = blockIdx.x * blockDim.x + threadIdx.x;
    const int total = N_NODES * (DIM / 4);
    if (i >= total) return;
    int n = i >> 5;
    int q = i & 31;
    float z = g_Z[(size_t)n * NUM_HEADS + (q >> 2)];
    float invz = 1.f / (z + 1e-6f);
    float4* p = reinterpret_cast<float4*>(out) + i;
    float4 v = *p;
    v.x *= invz; v.y *= invz; v.z *= invz; v.w *= invz;
    *p = v;
}

// ---------------------------------------------------------------------------
// kernel_launch
// ---------------------------------------------------------------------------
extern "C" void kernel_launch(void* const* d_in, const int* in_sizes, int n_in,
                              void* d_out, int out_size)
{
    const float* x         = (const float*)d_in[0];
    const float* edge_attr = (const float*)d_in[1];
    const int*   edge_idx  = (const int*)  d_in[2];
    const float* Wq = (const float*)d_in[3];
    const float* bq = (const float*)d_in[4];
    const float* Wk = (const float*)d_in[5];
    const float* bk = (const float*)d_in[6];
    const float* We = (const float*)d_in[7];
    const float* be = (const float*)d_in[8];
    const float* Wv = (const float*)d_in[9];
    const float* bv = (const float*)d_in[10];
    float* out = (float*)d_out;

    const int nNodes = in_sizes[0] / DIM;     // 50000
    const int nE     = in_sizes[1] / DIM;     // 800000

    cudaFuncSetAttribute(gemm_e_mma, cudaFuncAttributeMaxDynamicSharedMemorySize,
                         EMM_SMEM);

    // zero accumulators
    {
        size_t total = (size_t)nNodes * DIM;
        int threads = 256;
        int blocks = (int)((total + threads - 1) / threads);
        zero_kernel<<<blocks, threads>>>(out);
    }

    // Q, K, V projections (scalar fp32, fused launch)
    {
        dim3 grid((nNodes + BM - 1) / BM, 3);
        gemm_qkv<<<grid, 256>>>(x, Wq, bq, Wk, bk, Wv, bv, nNodes);
    }

    // E projection on tensor cores via mma.sync bf16x3
    {
        int blocks = (nE + 127) / 128;        // 6250
        gemm_e_mma<<<blocks, 256, EMM_SMEM>>>(edge_attr, We, be, nE);
    }

    // edge attention + scatter (high-occupancy standalone kernel)
    {
        int blocks = 148 * 8;
        edge_kernel<<<blocks, 256>>>(edge_idx, out, nE);
    }

    // normalize
    {
        int total = nNodes * (DIM / 4);
        int threads = 256;
        int blocks = (total + threads - 1) / threads;
        norm_kernel<<<blocks, threads>>>(out);
    }
}